// round 12
// baseline (speedup 1.0000x reference)
#include <cuda_runtime.h>
#include <cstdint>

#define BATCH 32
#define NH    16
#define DK    64
#define DM    1024
#define TC    4096

// Scratch (device globals — no allocation allowed in kernel_launch)
__device__ float g_qp[BATCH * DM];   // scaled query projection
__device__ float g_kp[BATCH * DM];   // new-token key projection
__device__ float g_vp[BATCH * DM];   // new-token value projection
__device__ float g_x [BATCH * DM];   // attention output (pre out-proj)

// Packed dual-FMA (sm_103a FFMA2; PTX-only, ptxas never emits from scalar C++)
__device__ __forceinline__ void ffma2(unsigned long long& d,
                                      unsigned long long a,
                                      unsigned long long b)
{
    asm("fma.rn.f32x2 %0, %1, %2, %0;" : "+l"(d) : "l"(a), "l"(b));
}

__device__ __forceinline__ float pair_sum(unsigned long long v)
{
    return __uint_as_float((unsigned)v) + __uint_as_float((unsigned)(v >> 32));
}

__device__ __forceinline__ void cp16(uint32_t smem_dst, const float* gsrc)
{
    asm volatile("cp.async.cg.shared.global [%0], [%1], 16;"
                 :: "r"(smem_dst), "l"(gsrc) : "memory");
}

// ---------------------------------------------------------------------------
// GEMV projection, fully-async staging: grid = (DM/8, nmat, 2), block 128.
// CTA owns 8 weight rows x 16 batches. ALL loads are cp.async (register-free,
// unbounded depth): weights (32KB, group 0) + 4 act groups of 4 batches
// (16KB each, groups 1..4) are committed at CTA start — every resident CTA
// keeps ~96KB in flight, so the DRAM pipe stays fed across the whole kernel
// instead of only during brief per-wave load phases (the R7-R11 limiter:
// duration == weight_bytes / phase-starved BW). Compute consumes groups
// progressively via cp.async.wait_group 4..0. FFMA2 inner product.
// mode 0: QKV — grid.y selects {wq->g_qp (*qscale), wk->g_kp, wv->g_vp}
// mode 1: out-projection — act = g_x (device symbol), W0/B0 -> out_ext
// ---------------------------------------------------------------------------
__global__ void __launch_bounds__(128)
proj_kernel(int mode,
            const float* __restrict__ act_ext,
            const float* __restrict__ W0, const float* __restrict__ B0,
            const float* __restrict__ W1, const float* __restrict__ B1,
            const float* __restrict__ W2, const float* __restrict__ B2,
            float* __restrict__ out_ext,
            float qscale)
{
    extern __shared__ __align__(16) float smem[];
    float* s_w   = smem;            // 8 rows x DM   = 32 KB
    float* s_act = smem + 8 * DM;   // 16 batch x DM = 64 KB

    const float* act;
    const float* W;
    const float* bias;
    float* out;
    float scale = 1.0f;

    if (mode == 1) {
        act = g_x;  W = W0; bias = B0; out = out_ext;
    } else {
        act = act_ext;
        if (blockIdx.y == 0)      { W = W0; bias = B0; out = g_qp; scale = qscale; }
        else if (blockIdx.y == 1) { W = W1; bias = B1; out = g_kp; }
        else                      { W = W2; bias = B2; out = g_vp; }
    }

    const int tid  = threadIdx.x;
    const int warp = tid >> 5;
    const int lane = tid & 31;
    const int j0   = (blockIdx.x * 4 + warp) * 2;   // 2 rows per warp
    const int b0   = blockIdx.z * 16;               // 16 batches per z-slice

    // ---- commit ALL copies up front (5 groups) ----
    {
        const float* Wbase = W + (size_t)(blockIdx.x * 8) * DM;
        uint32_t swb = (uint32_t)__cvta_generic_to_shared(s_w);
        uint32_t sab = (uint32_t)__cvta_generic_to_shared(s_act);
#pragma unroll
        for (int i = 0; i < 16; i++) {              // weights: 2048 x 16B
            int u = i * 128 + tid;
            cp16(swb + u * 16, Wbase + u * 4);
        }
        asm volatile("cp.async.commit_group;" ::: "memory");   // group W
#pragma unroll
        for (int g = 0; g < 4; g++) {               // act: 4 groups x 1024 x 16B
            const float* src = act + (size_t)(b0 + g * 4) * DM;
#pragma unroll
            for (int i = 0; i < 8; i++) {
                int u = i * 128 + tid;
                cp16(sab + (g * 4 * DM + u * 4) * 4, src + u * 4);
            }
            asm volatile("cp.async.commit_group;" ::: "memory"); // groups A0..A3
        }
    }

    const float bias0 = bias[j0], bias1 = bias[j0 + 1];

    // ---- weights ready (4 act groups may still be pending) ----
    asm volatile("cp.async.wait_group 4;" ::: "memory");
    __syncthreads();

    ulonglong2 w[2][8];
#pragma unroll
    for (int r = 0; r < 2; r++)
#pragma unroll
        for (int c = 0; c < 8; c++)
            w[r][c] = *(const ulonglong2*)&s_w[(warp * 2 + r) * DM + c * 128 + lane * 4];

#pragma unroll
    for (int g = 0; g < 4; g++) {
        // act group g arrived when <= (3-g) groups remain pending
        switch (g) {
            case 0: asm volatile("cp.async.wait_group 3;" ::: "memory"); break;
            case 1: asm volatile("cp.async.wait_group 2;" ::: "memory"); break;
            case 2: asm volatile("cp.async.wait_group 1;" ::: "memory"); break;
            default: asm volatile("cp.async.wait_group 0;" ::: "memory"); break;
        }
        __syncthreads();

        const float* sa = s_act + g * 4 * DM;
        unsigned long long a2[4][2];
#pragma unroll
        for (int b = 0; b < 4; b++) { a2[b][0] = 0ull; a2[b][1] = 0ull; }

#pragma unroll
        for (int c = 0; c < 8; c++) {
#pragma unroll
            for (int b = 0; b < 4; b++) {
                ulonglong2 x = *(const ulonglong2*)&sa[b * DM + c * 128 + lane * 4];
                ffma2(a2[b][0], x.x, w[0][c].x);
                ffma2(a2[b][0], x.y, w[0][c].y);
                ffma2(a2[b][1], x.x, w[1][c].x);
                ffma2(a2[b][1], x.y, w[1][c].y);
            }
        }

        float a[4][2];
#pragma unroll
        for (int b = 0; b < 4; b++) {
            a[b][0] = pair_sum(a2[b][0]);
            a[b][1] = pair_sum(a2[b][1]);
        }
#pragma unroll
        for (int off = 16; off; off >>= 1) {
#pragma unroll
            for (int b = 0; b < 4; b++) {
                a[b][0] += __shfl_xor_sync(0xffffffffu, a[b][0], off);
                a[b][1] += __shfl_xor_sync(0xffffffffu, a[b][1], off);
            }
        }

        if (lane == 0) {
            const int bb0 = b0 + g * 4;
#pragma unroll
            for (int b = 0; b < 4; b++) {
                out[(size_t)(bb0 + b) * DM + j0]     = (a[b][0] + bias0) * scale;
                out[(size_t)(bb0 + b) * DM + j0 + 1] = (a[b][1] + bias1) * scale;
            }
        }
    }
}

// ---------------------------------------------------------------------------
// Flash-decode attention over 4096 cached keys + 1 new token (R7-proven,
// at HBM roofline ~7.2 TB/s — UNCHANGED).
// One CTA per (b,h): 512 CTAs x 256 threads, single wave (4 CTAs/SM).
// float4 / half-warp layout; block-softmax over 4-key blocks per half.
// ---------------------------------------------------------------------------
__global__ void __launch_bounds__(256, 4)
attn_kernel(const float* __restrict__ Kc,
            const float* __restrict__ Vc)
{
    const int bh   = blockIdx.x;       // 0..511
    const int b    = bh >> 4;
    const int h    = bh & 15;
    const int warp = threadIdx.x >> 5;
    const int lane = threadIdx.x & 31;
    const int half = lane >> 4;        // 0 or 1
    const int li   = lane & 15;        // lane within half; dims 4*li..4*li+3

    __shared__ float4 sq[16];          // q, pre-scaled by 1/sqrt(DK)
    __shared__ float  sm[16], sl[16];
    __shared__ float4 so[16][16];

    if (threadIdx.x < 16)
        sq[threadIdx.x] = *(const float4*)(g_qp + b * DM + h * DK + 4 * threadIdx.x);
    __syncthreads();

    const float4 q4 = sq[li];

    const float* Kp = Kc + (size_t)bh * TC * DK + (size_t)half * DK + 4 * li;
    const float* Vp = Vc + (size_t)bh * TC * DK + (size_t)half * DK + 4 * li;

    float  m = -1e30f;
    float  l = 0.0f;
    float4 o = make_float4(0.f, 0.f, 0.f, 0.f);

    const int t0 = warp * (TC / 8);    // 512 keys per warp; 4/half per iter
    for (int t = t0; t < t0 + TC / 8; t += 8) {
        float4 kk[4], vv[4];
#pragma unroll
        for (int i = 0; i < 4; i++)
            kk[i] = __ldcs((const float4*)(Kp + (size_t)(t + 2 * i) * DK));
#pragma unroll
        for (int i = 0; i < 4; i++)
            vv[i] = __ldcs((const float4*)(Vp + (size_t)(t + 2 * i) * DK));

        float s[4];
#pragma unroll
        for (int i = 0; i < 4; i++)
            s[i] = kk[i].x * q4.x + kk[i].y * q4.y + kk[i].z * q4.z + kk[i].w * q4.w;
#pragma unroll
        for (int off = 8; off; off >>= 1)
#pragma unroll
            for (int i = 0; i < 4; i++)
                s[i] += __shfl_xor_sync(0xffffffffu, s[i], off);   // within half

        float bm = fmaxf(fmaxf(s[0], s[1]), fmaxf(s[2], s[3]));
        float mn = fmaxf(m, bm);

        float p[4];
#pragma unroll
        for (int i = 0; i < 4; i++) p[i] = __expf(s[i] - mn);

        float  lp = 0.0f;
        float4 op = make_float4(0.f, 0.f, 0.f, 0.f);
#pragma unroll
        for (int i = 0; i < 4; i++) {
            lp   += p[i];
            op.x += p[i] * vv[i].x;
            op.y += p[i] * vv[i].y;
            op.z += p[i] * vv[i].z;
            op.w += p[i] * vv[i].w;
        }

        float sc = __expf(m - mn);
        l   = l   * sc + lp;
        o.x = o.x * sc + op.x;
        o.y = o.y * sc + op.y;
        o.z = o.z * sc + op.z;
        o.w = o.w * sc + op.w;
        m   = mn;
    }

    // New (appended) token: warp 0 computes the score; half 0 folds it in.
    if (warp == 0) {
        float4 kk = *(const float4*)(g_kp + b * DM + h * DK + 4 * li);
        float4 vv = *(const float4*)(g_vp + b * DM + h * DK + 4 * li);
        float s = kk.x * q4.x + kk.y * q4.y + kk.z * q4.z + kk.w * q4.w;
#pragma unroll
        for (int off = 8; off; off >>= 1)
            s += __shfl_xor_sync(0xffffffffu, s, off);
        if (half == 0) {
            float mn = fmaxf(m, s);
            float sc = __expf(m - mn);
            float p  = __expf(s - mn);
            l   = l   * sc + p;
            o.x = o.x * sc + p * vv.x;
            o.y = o.y * sc + p * vv.y;
            o.z = o.z * sc + p * vv.z;
            o.w = o.w * sc + p * vv.w;
            m   = mn;
        }
    }

    const int idx = warp * 2 + half;   // 16 partial states
    if (li == 0) { sm[idx] = m; sl[idx] = l; }
    so[idx][li] = o;
    __syncthreads();

    // Combine 16 partial states; threads 0..63 each own one output dim.
    if (threadIdx.x < DK) {
        const int d = threadIdx.x;
        float M = sm[0];
#pragma unroll
        for (int i = 1; i < 16; i++) M = fmaxf(M, sm[i]);
        float L = 0.0f, O = 0.0f;
#pragma unroll
        for (int i = 0; i < 16; i++) {
            float e = __expf(sm[i] - M);
            L += e * sl[i];
            O += e * ((const float*)so[i])[d];
        }
        g_x[b * DM + h * DK + d] = O / L;
    }
}

// ---------------------------------------------------------------------------
// inputs (metadata order): 0 q, 1 key_pre, 2 value_pre,
//   3 wq, 4 bq, 5 wk, 6 bk, 7 wv, 8 bv, 9 wo, 10 bo
// output: [32, 1, 1024] fp32
// ---------------------------------------------------------------------------
extern "C" void kernel_launch(void* const* d_in, const int* in_sizes, int n_in,
                              void* d_out, int out_size)
{
    const float* q   = (const float*)d_in[0];
    const float* Kc  = (const float*)d_in[1];
    const float* Vc  = (const float*)d_in[2];
    const float* wq  = (const float*)d_in[3];
    const float* bq  = (const float*)d_in[4];
    const float* wk  = (const float*)d_in[5];
    const float* bk  = (const float*)d_in[6];
    const float* wv  = (const float*)d_in[7];
    const float* bv  = (const float*)d_in[8];
    const float* wo  = (const float*)d_in[9];
    const float* bo  = (const float*)d_in[10];
    float* out = (float*)d_out;

    const float qscale = 0.125f;  // 1/sqrt(DK)
    const int smem_bytes = (8 * DM + 16 * DM) * (int)sizeof(float);  // 96 KB

    // Host-side attribute set (idempotent, allocation-free, capture-safe).
    cudaFuncSetAttribute(proj_kernel,
                         cudaFuncAttributeMaxDynamicSharedMemorySize, smem_bytes);

    // QKV projections (grid.y selects matrix; q gets the softmax scale folded in)
    proj_kernel<<<dim3(DM / 8, 3, 2), 128, smem_bytes>>>(
        0, q, wq, bq, wk, bk, wv, bv, nullptr, qscale);

    // Flash-decode attention over the cache + appended token (single wave)
    attn_kernel<<<BATCH * NH, 256>>>(Kc, Vc);

    // Output projection: reads g_x via device-side symbol, writes d_out
    proj_kernel<<<dim3(DM / 8, 1, 2), 128, smem_bytes>>>(
        1, nullptr, wo, bo, nullptr, nullptr, nullptr, nullptr, out, 1.0f);
}